// round 15
// baseline (speedup 1.0000x reference)
#include <cuda_runtime.h>

#define V_   2048
#define L_   16
#define H_   8
#define D_   64
#define B_   8192
#define NN_  2048
#define TEMP_INV 0.125f
#define LN_EPS_ 1e-5f

// ---- device scratch ----
__device__ float     g_cqkv[V_ * 1536];   // (V, 3, H, D)
__device__ float     g_pqkv[L_ * 1536];   // (L, 3, H, D)
__device__ float     g_posqk[H_ * L_ * L_];
__device__ float     g_T1[V_ * H_ * L_];  // cq[v,h]·pk[j,h]
__device__ float     g_T2[V_ * H_ * L_];  // ck[v,h]·pq[j,h]
__device__ float     g_wordx[B_ * 512];
__device__ long long g_offs[NN_];
__device__ int       g_cnt[NN_];

// ============ kernel 1: pqkv = pos @ Wp + bp ============
__global__ void k_pqkv(const float* __restrict__ Wp, const float* __restrict__ bp) {
    __shared__ float pos[64];
    int l = blockIdx.x;
    int tid = threadIdx.x;
    if (tid < 64) {
        int d = tid;
        int f = d & 31;
        double inv = pow(10000.0, -(double)f / 32.0);
        double ph = (double)l * inv;
        pos[d] = (d < 32) ? (float)cos(ph) : (float)sin(ph);
    }
    __syncthreads();
    for (int o = tid; o < 1536; o += 256) {
        float acc = bp[o];
        #pragma unroll 16
        for (int d = 0; d < 64; d++) acc += pos[d] * Wp[d * 1536 + o];
        g_pqkv[l * 1536 + o] = acc;
    }
}

// ============ kernel 1b: pos_qk[h,i,j] = pq[i,h]·pk[j,h] ============
__global__ void k_posqk() {
    int h = blockIdx.x;
    int t = threadIdx.x;
    int i = t >> 4, j = t & 15;
    const float* pq = &g_pqkv[i * 1536 + h * 64];
    const float* pk = &g_pqkv[j * 1536 + 512 + h * 64];
    float acc = 0.f;
    #pragma unroll 16
    for (int d = 0; d < 64; d++) acc += pq[d] * pk[d];
    g_posqk[h * 256 + t] = acc;
}

// ============ kernel 2: cqkv = char_emb @ Wc + bc, FUSED with T1/T2 tables ============
__global__ __launch_bounds__(256) void k_cqkv(const float* __restrict__ emb,
                                              const float* __restrict__ Wc,
                                              const float* __restrict__ bc) {
    __shared__ float es[8][64];
    __shared__ float qs[8][1032];    // cq|ck for 8 v's
    int v0 = blockIdx.x * 8;
    int tid = threadIdx.x;
    for (int idx = tid; idx < 8 * 64; idx += 256) es[idx >> 6][idx & 63] = emb[v0 * 64 + idx];
    __syncthreads();
    int o[6];
    float acc[8][6];
    #pragma unroll
    for (int p = 0; p < 6; p++) {
        o[p] = tid + p * 256;
        float bv = bc[o[p]];
        #pragma unroll
        for (int r = 0; r < 8; r++) acc[r][p] = bv;
    }
    for (int d = 0; d < 64; d++) {
        float w[6];
        #pragma unroll
        for (int p = 0; p < 6; p++) w[p] = Wc[d * 1536 + o[p]];
        #pragma unroll
        for (int r = 0; r < 8; r++) {
            float e = es[r][d];
            #pragma unroll
            for (int p = 0; p < 6; p++) acc[r][p] += e * w[p];
        }
    }
    #pragma unroll
    for (int r = 0; r < 8; r++) {
        #pragma unroll
        for (int p = 0; p < 6; p++)
            g_cqkv[(v0 + r) * 1536 + o[p]] = acc[r][p];
        #pragma unroll
        for (int p = 0; p < 4; p++)          // o[p] < 1024: cq|ck region
            qs[r][o[p]] = acc[r][p];
    }
    __syncthreads();

    // ---- phase 2: T1/T2 for these 8 v's ----
    int tb = tid >> 7, h = (tid >> 4) & 7, j = tid & 15;
    float4 pr[16];
    const float* pb = &g_pqkv[j * 1536 + (tb ? 0 : 512) + h * 64];
    #pragma unroll
    for (int k4 = 0; k4 < 16; k4++) pr[k4] = *(const float4*)&pb[k4 * 4];

    float* dst = tb ? g_T2 : g_T1;
    #pragma unroll
    for (int v = 0; v < 8; v++) {
        const float* ab = &qs[v][tb * 512 + h * 64];
        float a = 0.f;
        #pragma unroll
        for (int k4 = 0; k4 < 16; k4++) {
            float4 f = *(const float4*)&ab[k4 * 4];
            a += f.x * pr[k4].x + f.y * pr[k4].y + f.z * pr[k4].z + f.w * pr[k4].w;
        }
        dst[(v0 + v) * 128 + h * 16 + j] = a;
    }
}

// ============ kernel 3: per-word attention + LN + pool + MLP (exact R10) ============
#define SMEM_FLOATS 9748
#define SMEM_BYTES  (SMEM_FLOATS * 4)

__global__ __launch_bounds__(256, 4) void k_word(const int* __restrict__ char_code,
                                                 const float* __restrict__ gamma,
                                                 const float* __restrict__ beta,
                                                 const float* __restrict__ W1,
                                                 const float* __restrict__ b1,
                                                 const float* __restrict__ W2,
                                                 const float* __restrict__ b2) {
    extern __shared__ float sm[];
    float* As      = sm;
    float* Bs      = sm + 4608;
    float* Vs      = sm;               // reuse after sim GEMM
    float* pooledS = sm + 9216;
    int*   codes   = (int*)(sm + 9728);
    float* fnmask  = sm + 9744;

    int b = blockIdx.x;
    int tid = threadIdx.x;

    if (tid < 16) codes[tid] = char_code[b * 16 + tid];
    __syncthreads();
    if (tid == 0) {
        int c = 0;
        #pragma unroll
        for (int i = 0; i < 16; i++) c += (codes[i] != 0);
        *fnmask = (float)c;
    }

    int lane = tid & 31;
    int h = tid >> 5;                 // warp == head
    int igrp = lane >> 3, jgrp = lane & 7;
    int i0 = igrp * 4, j0 = jgrp * 2;

    int ci_r[4];
    #pragma unroll
    for (int ii = 0; ii < 4; ii++) ci_r[ii] = codes[i0 + ii];
    int cj0 = codes[j0], cj1 = codes[j0 + 1];

    // ---- acc init from tables ----
    float acc[4][2];
    #pragma unroll
    for (int ii = 0; ii < 4; ii++) {
        const float* t1 = &g_T1[ci_r[ii] * 128 + h * 16];
        acc[ii][0] = g_posqk[h * 256 + (i0 + ii) * 16 + j0]     + t1[j0]     + g_T2[cj0 * 128 + h * 16 + i0 + ii];
        acc[ii][1] = g_posqk[h * 256 + (i0 + ii) * 16 + j0 + 1] + t1[j0 + 1] + g_T2[cj1 * 128 + h * 16 + i0 + ii];
    }

    // ---- sim GEMM, K split into two 32-chunks ----
    #pragma unroll
    for (int c = 0; c < 2; c++) {
        if (c == 1) __syncthreads();   // chunk-0 reads done before overwrite
        for (int idx = tid; idx < 8 * 16 * 8; idx += 256) {
            int kk = idx & 7, i = (idx >> 3) & 15, hh = idx >> 7;
            int ci = codes[i];
            float4 fa = *(const float4*)&g_cqkv[ci * 1536 + hh * 64 + c * 32 + kk * 4];
            *(float4*)&As[(hh * 16 + i) * 36 + kk * 4] = fa;
            float4 fb = *(const float4*)&g_cqkv[ci * 1536 + 512 + hh * 64 + c * 32 + kk * 4];
            *(float4*)&Bs[(hh * 16 + i) * 36 + kk * 4] = fb;
        }
        __syncthreads();

        const float* Ab = &As[(h * 16) * 36];
        const float* Bb = &Bs[(h * 16) * 36];
        #pragma unroll
        for (int k = 0; k < 32; k += 4) {
            float4 a[4], bv[2];
            #pragma unroll
            for (int ii = 0; ii < 4; ii++) a[ii] = *(const float4*)&Ab[(i0 + ii) * 36 + k];
            #pragma unroll
            for (int jj = 0; jj < 2; jj++) bv[jj] = *(const float4*)&Bb[(j0 + jj) * 36 + k];
            #pragma unroll
            for (int ii = 0; ii < 4; ii++)
                #pragma unroll
                for (int jj = 0; jj < 2; jj++)
                    acc[ii][jj] += a[ii].x * bv[jj].x + a[ii].y * bv[jj].y +
                                   a[ii].z * bv[jj].z + a[ii].w * bv[jj].w;
        }
    }

    // ---- scale, mask, softmax (no max pass; masked -> exact 0) ----
    bool m0 = (cj0 == 0), m1 = (cj1 == 0);
    float p0[4], p1[4];
    #pragma unroll
    for (int ii = 0; ii < 4; ii++) {
        float e0 = m0 ? 0.f : __expf(acc[ii][0] * TEMP_INV);
        float e1 = m1 ? 0.f : __expf(acc[ii][1] * TEMP_INV);
        float sum = e0 + e1;
        sum += __shfl_xor_sync(0xffffffffu, sum, 1);
        sum += __shfl_xor_sync(0xffffffffu, sum, 2);
        sum += __shfl_xor_sync(0xffffffffu, sum, 4);
        float inv = 1.0f / sum;
        p0[ii] = e0 * inv;
        p1[ii] = e1 * inv;
    }

    // ---- stage V = cv + pv into reused buffer ----
    __syncthreads();   // all warps done reading A/B
    for (int idx = tid; idx < 8 * 16 * 16; idx += 256) {
        int kk = idx & 15, i = (idx >> 4) & 15, hh = idx >> 8;
        int ci = codes[i];
        float4 fv = *(const float4*)&g_cqkv[ci * 1536 + 1024 + hh * 64 + kk * 4];
        float4 fp = *(const float4*)&g_pqkv[i * 1536 + 1024 + hh * 64 + kk * 4];
        fv.x += fp.x; fv.y += fp.y; fv.z += fp.z; fv.w += fp.w;
        *(float4*)&Vs[(hh * 16 + i) * 64 + kk * 4] = fv;
    }
    __syncthreads();

    // ---- out GEMM: out[16][64] = attn @ V, attn via shfl ----
    int dgrp = lane & 7;
    int d0 = dgrp * 8;
    float oacc[4][8];
    #pragma unroll
    for (int ii = 0; ii < 4; ii++)
        #pragma unroll
        for (int dd = 0; dd < 8; dd++) oacc[ii][dd] = 0.f;

    const float* Vb = &Vs[(h * 16) * 64];
    #pragma unroll
    for (int j = 0; j < 16; j++) {
        int src = (lane & 24) | (j >> 1);
        float av[4];
        #pragma unroll
        for (int ii = 0; ii < 4; ii++)
            av[ii] = __shfl_sync(0xffffffffu, (j & 1) ? p1[ii] : p0[ii], src);
        float4 v0 = *(const float4*)&Vb[j * 64 + d0];
        float4 v1 = *(const float4*)&Vb[j * 64 + d0 + 4];
        #pragma unroll
        for (int ii = 0; ii < 4; ii++) {
            oacc[ii][0] += av[ii] * v0.x;  oacc[ii][1] += av[ii] * v0.y;
            oacc[ii][2] += av[ii] * v0.z;  oacc[ii][3] += av[ii] * v0.w;
            oacc[ii][4] += av[ii] * v1.x;  oacc[ii][5] += av[ii] * v1.y;
            oacc[ii][6] += av[ii] * v1.z;  oacc[ii][7] += av[ii] * v1.w;
        }
    }

    // ---- LayerNorm over d + masked pool ----
    float garr[8], barr[8];
    #pragma unroll
    for (int dd = 0; dd < 8; dd++) { garr[dd] = gamma[d0 + dd]; barr[dd] = beta[d0 + dd]; }

    float pl[8];
    #pragma unroll
    for (int dd = 0; dd < 8; dd++) pl[dd] = 0.f;

    #pragma unroll
    for (int ii = 0; ii < 4; ii++) {
        float lsum = 0.f, lsq = 0.f;
        #pragma unroll
        for (int dd = 0; dd < 8; dd++) { float x = oacc[ii][dd]; lsum += x; lsq += x * x; }
        lsum += __shfl_xor_sync(0xffffffffu, lsum, 1);
        lsum += __shfl_xor_sync(0xffffffffu, lsum, 2);
        lsum += __shfl_xor_sync(0xffffffffu, lsum, 4);
        lsq  += __shfl_xor_sync(0xffffffffu, lsq, 1);
        lsq  += __shfl_xor_sync(0xffffffffu, lsq, 2);
        lsq  += __shfl_xor_sync(0xffffffffu, lsq, 4);
        float mean = lsum * (1.f / 64.f);
        float var  = lsq * (1.f / 64.f) - mean * mean;
        float rstd = rsqrtf(var + LN_EPS_);
        float mk = (codes[i0 + ii] != 0) ? 1.f : 0.f;
        #pragma unroll
        for (int dd = 0; dd < 8; dd++) {
            float nv = (oacc[ii][dd] - mean) * rstd * garr[dd] + barr[dd];
            pl[dd] += mk * nv;
        }
    }
    #pragma unroll
    for (int dd = 0; dd < 8; dd++) {
        pl[dd] += __shfl_xor_sync(0xffffffffu, pl[dd], 8);
        pl[dd] += __shfl_xor_sync(0xffffffffu, pl[dd], 16);
    }
    if (igrp == 0) {
        float invn = 1.0f / *fnmask;
        #pragma unroll
        for (int dd = 0; dd < 8; dd++) pooledS[h * 64 + d0 + dd] = pl[dd] * invn;
    }
    __syncthreads();

    // ---- MLP per d ----
    if (tid < 64) {
        int d = tid;
        float x[8];
        #pragma unroll
        for (int h2 = 0; h2 < 8; h2++) x[h2] = pooledS[h2 * 64 + d];
        float y1[16];
        #pragma unroll
        for (int k = 0; k < 16; k++) {
            float a = b1[k];
            #pragma unroll
            for (int h2 = 0; h2 < 8; h2++) a += x[h2] * W1[h2 * 16 + k];
            y1[k] = fmaxf(a, 0.f);
        }
        float y2[8];
        #pragma unroll
        for (int m = 0; m < 8; m++) {
            float a = b2[m];
            #pragma unroll
            for (int k = 0; k < 16; k++) a += y1[k] * W2[k * 8 + m];
            y2[m] = a;
        }
        float4* outp = (float4*)&g_wordx[b * 512 + d * 8];
        outp[0] = make_float4(y2[0], y2[1], y2[2], y2[3]);
        outp[1] = make_float4(y2[4], y2[5], y2[6], y2[7]);
    }
}

// ============ kernel 4: PARALLEL counts + exclusive offsets (dtype-robust) ============
// 256 threads x 8 entries, coalesced. ok-check via __syncthreads_and.
__global__ void k_scan(const void* __restrict__ nw_raw, int total) {
    __shared__ long long part[257];
    int t = threadIdx.x;
    const int* p32 = (const int*)nw_raw;

    int v[8];
    long long s = 0;
    bool ok = true;
    #pragma unroll
    for (int k = 0; k < 8; k++) {
        v[k] = p32[t * 8 + k];
        ok = ok && (v[k] >= 0) && (v[k] <= total);
        s += v[k];
    }
    int allok = __syncthreads_and(ok ? 1 : 0);
    part[t] = s;
    __syncthreads();
    if (t == 0) {
        long long a = 0;
        for (int i = 0; i < 256; i++) { long long tmp = part[i]; part[i] = a; a += tmp; }
        part[256] = a;
    }
    __syncthreads();
    bool use32 = allok && (part[256] == (long long)total);

    if (use32) {
        long long a = part[t];
        #pragma unroll
        for (int k = 0; k < 8; k++) {
            g_cnt[t * 8 + k] = v[k];
            g_offs[t * 8 + k] = a;
            a += v[k];
        }
    } else {
        const long long* p64 = (const long long*)nw_raw;
        long long w[8];
        long long s2 = 0;
        #pragma unroll
        for (int k = 0; k < 8; k++) { w[k] = p64[t * 8 + k]; s2 += w[k]; }
        __syncthreads();
        part[t] = s2;
        __syncthreads();
        if (t == 0) {
            long long a = 0;
            for (int i = 0; i < 256; i++) { long long tmp = part[i]; part[i] = a; a += tmp; }
        }
        __syncthreads();
        long long a = part[t];
        #pragma unroll
        for (int k = 0; k < 8; k++) {
            g_cnt[t * 8 + k] = (int)w[k];
            g_offs[t * 8 + k] = a;
            a += w[k];
        }
    }
}

// ============ kernel 5: name segment means (vectorized, 128 threads) ============
__global__ void k_name(const int* __restrict__ word_code,
                       float* __restrict__ out) {
    int n = blockIdx.x;
    int t = threadIdx.x;          // 128 threads, each owns 4 consecutive cols
    int cnt = g_cnt[n];
    long long off = g_offs[n];
    float inv = 1.0f / (float)cnt;
    int c = t * 4;
    float4 acc = make_float4(0.f, 0.f, 0.f, 0.f);
    for (int k = 0; k < cnt; k++) {
        int w = word_code[off + k];
        float4 v = *(const float4*)&g_wordx[w * 512 + c];
        acc.x += v.x; acc.y += v.y; acc.z += v.z; acc.w += v.w;
    }
    acc.x *= inv; acc.y *= inv; acc.z *= inv; acc.w *= inv;
    *(float4*)&out[n * 512 + c] = acc;
}

extern "C" void kernel_launch(void* const* d_in, const int* in_sizes, int n_in,
                              void* d_out, int out_size) {
    const float* char_emb = (const float*)d_in[0];
    const float* Wc       = (const float*)d_in[1];
    const float* bc       = (const float*)d_in[2];
    const float* Wp       = (const float*)d_in[3];
    const float* bp       = (const float*)d_in[4];
    const float* gamma    = (const float*)d_in[5];
    const float* beta     = (const float*)d_in[6];
    const float* W1       = (const float*)d_in[7];
    const float* b1       = (const float*)d_in[8];
    const float* W2       = (const float*)d_in[9];
    const float* b2       = (const float*)d_in[10];
    const int* char_code  = (const int*)d_in[11];
    const int* word_code  = (const int*)d_in[12];
    const void* n_words   = d_in[13];
    (void)n_in; (void)out_size;

    int total_words = in_sizes[12];

    k_pqkv<<<L_, 256>>>(Wp, bp);
    k_posqk<<<H_, 256>>>();
    k_cqkv<<<V_ / 8, 256>>>(char_emb, Wc, bc);   // fused cqkv + T1/T2
    k_scan<<<1, 256>>>(n_words, total_words);     // parallel now
    k_word<<<B_, 256, SMEM_BYTES>>>(char_code, gamma, beta, W1, b1, W2, b2);
    k_name<<<NN_, 128>>>(word_code, (float*)d_out);
}

// round 16
// speedup vs baseline: 1.2788x; 1.2788x over previous
#include <cuda_runtime.h>
#include <cuda_fp16.h>

#define V_   2048
#define L_   16
#define H_   8
#define D_   64
#define B_   8192
#define NN_  2048
#define TEMP_INV 0.125f
#define LN_EPS_ 1e-5f

// ---- device scratch ----
__device__ float     g_cqkv[V_ * 1536];   // (V, 3, H, D)
__device__ float     g_pqkv[L_ * 1536];   // (L, 3, H, D)
__device__ float     g_posqk[H_ * L_ * L_];
__device__ float     g_T1[V_ * H_ * L_];  // cq[v,h]·pk[j,h]
__device__ float     g_T2[V_ * H_ * L_];  // ck[v,h]·pq[j,h]
__device__ __half    g_gram[(size_t)H_ * V_ * V_];   // 64MB: cq[x,h]·ck[y,h]
__device__ float     g_wordx[B_ * 512];
__device__ long long g_offs[NN_];
__device__ int       g_cnt[NN_];

// ============ kernel 1: pqkv = pos @ Wp + bp ============
__global__ void k_pqkv(const float* __restrict__ Wp, const float* __restrict__ bp) {
    __shared__ float pos[64];
    int l = blockIdx.x;
    int tid = threadIdx.x;
    if (tid < 64) {
        int d = tid;
        int f = d & 31;
        double inv = pow(10000.0, -(double)f / 32.0);
        double ph = (double)l * inv;
        pos[d] = (d < 32) ? (float)cos(ph) : (float)sin(ph);
    }
    __syncthreads();
    for (int o = tid; o < 1536; o += 256) {
        float acc = bp[o];
        #pragma unroll 16
        for (int d = 0; d < 64; d++) acc += pos[d] * Wp[d * 1536 + o];
        g_pqkv[l * 1536 + o] = acc;
    }
}

// ============ kernel 1b: pos_qk[h,i,j] = pq[i,h]·pk[j,h] ============
__global__ void k_posqk() {
    int h = blockIdx.x;
    int t = threadIdx.x;
    int i = t >> 4, j = t & 15;
    const float* pq = &g_pqkv[i * 1536 + h * 64];
    const float* pk = &g_pqkv[j * 1536 + 512 + h * 64];
    float acc = 0.f;
    #pragma unroll 16
    for (int d = 0; d < 64; d++) acc += pq[d] * pk[d];
    g_posqk[h * 256 + t] = acc;
}

// ============ kernel 2: cqkv = char_emb @ Wc + bc, FUSED with T1/T2 tables ============
__global__ __launch_bounds__(256) void k_cqkv(const float* __restrict__ emb,
                                              const float* __restrict__ Wc,
                                              const float* __restrict__ bc) {
    __shared__ float es[8][64];
    __shared__ float qs[8][1032];    // cq|ck for 8 v's
    int v0 = blockIdx.x * 8;
    int tid = threadIdx.x;
    for (int idx = tid; idx < 8 * 64; idx += 256) es[idx >> 6][idx & 63] = emb[v0 * 64 + idx];
    __syncthreads();
    int o[6];
    float acc[8][6];
    #pragma unroll
    for (int p = 0; p < 6; p++) {
        o[p] = tid + p * 256;
        float bv = bc[o[p]];
        #pragma unroll
        for (int r = 0; r < 8; r++) acc[r][p] = bv;
    }
    for (int d = 0; d < 64; d++) {
        float w[6];
        #pragma unroll
        for (int p = 0; p < 6; p++) w[p] = Wc[d * 1536 + o[p]];
        #pragma unroll
        for (int r = 0; r < 8; r++) {
            float e = es[r][d];
            #pragma unroll
            for (int p = 0; p < 6; p++) acc[r][p] += e * w[p];
        }
    }
    #pragma unroll
    for (int r = 0; r < 8; r++) {
        #pragma unroll
        for (int p = 0; p < 6; p++)
            g_cqkv[(v0 + r) * 1536 + o[p]] = acc[r][p];
        #pragma unroll
        for (int p = 0; p < 4; p++)          // o[p] < 1024: cq|ck region
            qs[r][o[p]] = acc[r][p];
    }
    __syncthreads();

    // ---- phase 2: T1/T2 for these 8 v's ----
    int tb = tid >> 7, h = (tid >> 4) & 7, j = tid & 15;
    float4 pr[16];
    const float* pb = &g_pqkv[j * 1536 + (tb ? 0 : 512) + h * 64];
    #pragma unroll
    for (int k4 = 0; k4 < 16; k4++) pr[k4] = *(const float4*)&pb[k4 * 4];

    float* dst = tb ? g_T2 : g_T1;
    #pragma unroll
    for (int v = 0; v < 8; v++) {
        const float* ab = &qs[v][tb * 512 + h * 64];
        float a = 0.f;
        #pragma unroll
        for (int k4 = 0; k4 < 16; k4++) {
            float4 f = *(const float4*)&ab[k4 * 4];
            a += f.x * pr[k4].x + f.y * pr[k4].y + f.z * pr[k4].z + f.w * pr[k4].w;
        }
        dst[(v0 + v) * 128 + h * 16 + j] = a;
    }
}

// ============ kernel 2c: gram table S[h,x,y] = cq[x,h]·ck[y,h] (fp16 out) ============
// grid (16,16,8): 128x128 tile per block. smem transposed [d][x] for conflict-free reads.
__global__ __launch_bounds__(256) void k_gram() {
    __shared__ float As[64 * 128];   // [d][x-local]
    __shared__ float Bs[64 * 128];   // [d][y-local]
    int x0 = blockIdx.x * 128, y0 = blockIdx.y * 128, h = blockIdx.z;
    int tid = threadIdx.x;

    for (int idx = tid; idx < 2048; idx += 256) {
        int row = idx & 127, k4 = idx >> 7;   // k4 in 0..15
        float4 fa = *(const float4*)&g_cqkv[(x0 + row) * 1536 + h * 64 + k4 * 4];
        As[(k4 * 4 + 0) * 128 + row] = fa.x;
        As[(k4 * 4 + 1) * 128 + row] = fa.y;
        As[(k4 * 4 + 2) * 128 + row] = fa.z;
        As[(k4 * 4 + 3) * 128 + row] = fa.w;
        float4 fb = *(const float4*)&g_cqkv[(y0 + row) * 1536 + 512 + h * 64 + k4 * 4];
        Bs[(k4 * 4 + 0) * 128 + row] = fb.x;
        Bs[(k4 * 4 + 1) * 128 + row] = fb.y;
        Bs[(k4 * 4 + 2) * 128 + row] = fb.z;
        Bs[(k4 * 4 + 3) * 128 + row] = fb.w;
    }
    __syncthreads();

    int tx = tid & 15, ty = tid >> 4;
    // thread covers x in {tx*4..tx*4+3} ∪ {64+tx*4..}, y likewise with ty
    float acc[8][8];
    #pragma unroll
    for (int i = 0; i < 8; i++)
        #pragma unroll
        for (int j = 0; j < 8; j++) acc[i][j] = 0.f;

    #pragma unroll 4
    for (int d = 0; d < 64; d++) {
        float4 a0 = *(const float4*)&As[d * 128 + tx * 4];
        float4 a1 = *(const float4*)&As[d * 128 + 64 + tx * 4];
        float4 b0 = *(const float4*)&Bs[d * 128 + ty * 4];
        float4 b1 = *(const float4*)&Bs[d * 128 + 64 + ty * 4];
        float av[8] = {a0.x, a0.y, a0.z, a0.w, a1.x, a1.y, a1.z, a1.w};
        float bv[8] = {b0.x, b0.y, b0.z, b0.w, b1.x, b1.y, b1.z, b1.w};
        #pragma unroll
        for (int i = 0; i < 8; i++)
            #pragma unroll
            for (int j = 0; j < 8; j++) acc[i][j] += av[i] * bv[j];
    }

    #pragma unroll
    for (int i = 0; i < 8; i++) {
        int gx = x0 + ((i < 4) ? (tx * 4 + i) : (64 + tx * 4 + i - 4));
        __half2* rowp = (__half2*)&g_gram[((size_t)((h << 11) + gx) << 11)];
        int yb0 = (y0 + ty * 4) >> 1;        // half2 index for first y-group (even base)
        int yb1 = (y0 + 64 + ty * 4) >> 1;
        rowp[yb0]     = __floats2half2_rn(acc[i][0], acc[i][1]);
        rowp[yb0 + 1] = __floats2half2_rn(acc[i][2], acc[i][3]);
        rowp[yb1]     = __floats2half2_rn(acc[i][4], acc[i][5]);
        rowp[yb1 + 1] = __floats2half2_rn(acc[i][6], acc[i][7]);
    }
}

// ============ kernel 3: per-word attention (gram-gather) + LN + pool + MLP ============
// smem (floats): Vs[8][16][64] @0 (8192), pooledS @8192 (512), codes @8704, fnmask @8720
#define SMEM_FLOATS 8724
#define SMEM_BYTES  (SMEM_FLOATS * 4)

__global__ __launch_bounds__(256, 4) void k_word(const int* __restrict__ char_code,
                                                 const float* __restrict__ gamma,
                                                 const float* __restrict__ beta,
                                                 const float* __restrict__ W1,
                                                 const float* __restrict__ b1,
                                                 const float* __restrict__ W2,
                                                 const float* __restrict__ b2) {
    extern __shared__ float sm[];
    float* Vs      = sm;
    float* pooledS = sm + 8192;
    int*   codes   = (int*)(sm + 8704);
    float* fnmask  = sm + 8720;

    int b = blockIdx.x;
    int tid = threadIdx.x;

    if (tid < 16) codes[tid] = char_code[b * 16 + tid];
    __syncthreads();
    if (tid == 0) {
        int c = 0;
        #pragma unroll
        for (int i = 0; i < 16; i++) c += (codes[i] != 0);
        *fnmask = (float)c;
    }

    int lane = tid & 31;
    int h = tid >> 5;                 // warp == head
    int igrp = lane >> 3, jgrp = lane & 7;
    int i0 = igrp * 4, j0 = jgrp * 2;

    int ci_r[4];
    #pragma unroll
    for (int ii = 0; ii < 4; ii++) ci_r[ii] = codes[i0 + ii];
    int cj0 = codes[j0], cj1 = codes[j0 + 1];

    // ---- full logits from tables: posqk + T1 + T2 + gram ----
    float acc[4][2];
    #pragma unroll
    for (int ii = 0; ii < 4; ii++) {
        const float* t1 = &g_T1[ci_r[ii] * 128 + h * 16];
        const __half* gr = &g_gram[((size_t)((h << 11) + ci_r[ii]) << 11)];
        acc[ii][0] = g_posqk[h * 256 + (i0 + ii) * 16 + j0]     + t1[j0]
                   + g_T2[cj0 * 128 + h * 16 + i0 + ii] + __half2float(gr[cj0]);
        acc[ii][1] = g_posqk[h * 256 + (i0 + ii) * 16 + j0 + 1] + t1[j0 + 1]
                   + g_T2[cj1 * 128 + h * 16 + i0 + ii] + __half2float(gr[cj1]);
    }

    // ---- stage V = cv + pv (overlaps gram-load latency via separate warps) ----
    for (int idx = tid; idx < 8 * 16 * 16; idx += 256) {
        int kk = idx & 15, i = (idx >> 4) & 15, hh = idx >> 8;
        int ci = codes[i];
        float4 fv = *(const float4*)&g_cqkv[ci * 1536 + 1024 + hh * 64 + kk * 4];
        float4 fp = *(const float4*)&g_pqkv[i * 1536 + 1024 + hh * 64 + kk * 4];
        fv.x += fp.x; fv.y += fp.y; fv.z += fp.z; fv.w += fp.w;
        *(float4*)&Vs[(hh * 16 + i) * 64 + kk * 4] = fv;
    }

    // ---- scale, mask, softmax (no max pass; masked -> exact 0) ----
    bool m0 = (cj0 == 0), m1 = (cj1 == 0);
    float p0[4], p1[4];
    #pragma unroll
    for (int ii = 0; ii < 4; ii++) {
        float e0 = m0 ? 0.f : __expf(acc[ii][0] * TEMP_INV);
        float e1 = m1 ? 0.f : __expf(acc[ii][1] * TEMP_INV);
        float sum = e0 + e1;
        sum += __shfl_xor_sync(0xffffffffu, sum, 1);
        sum += __shfl_xor_sync(0xffffffffu, sum, 2);
        sum += __shfl_xor_sync(0xffffffffu, sum, 4);
        float inv = 1.0f / sum;
        p0[ii] = e0 * inv;
        p1[ii] = e1 * inv;
    }
    __syncthreads();   // V staged

    // ---- out GEMM: out[16][64] = attn @ V, attn via shfl ----
    int dgrp = lane & 7;
    int d0 = dgrp * 8;
    float oacc[4][8];
    #pragma unroll
    for (int ii = 0; ii < 4; ii++)
        #pragma unroll
        for (int dd = 0; dd < 8; dd++) oacc[ii][dd] = 0.f;

    const float* Vb = &Vs[(h * 16) * 64];
    #pragma unroll
    for (int j = 0; j < 16; j++) {
        int src = (lane & 24) | (j >> 1);
        float av[4];
        #pragma unroll
        for (int ii = 0; ii < 4; ii++)
            av[ii] = __shfl_sync(0xffffffffu, (j & 1) ? p1[ii] : p0[ii], src);
        float4 v0 = *(const float4*)&Vb[j * 64 + d0];
        float4 v1 = *(const float4*)&Vb[j * 64 + d0 + 4];
        #pragma unroll
        for (int ii = 0; ii < 4; ii++) {
            oacc[ii][0] += av[ii] * v0.x;  oacc[ii][1] += av[ii] * v0.y;
            oacc[ii][2] += av[ii] * v0.z;  oacc[ii][3] += av[ii] * v0.w;
            oacc[ii][4] += av[ii] * v1.x;  oacc[ii][5] += av[ii] * v1.y;
            oacc[ii][6] += av[ii] * v1.z;  oacc[ii][7] += av[ii] * v1.w;
        }
    }

    // ---- LayerNorm over d + masked pool ----
    float garr[8], barr[8];
    #pragma unroll
    for (int dd = 0; dd < 8; dd++) { garr[dd] = gamma[d0 + dd]; barr[dd] = beta[d0 + dd]; }

    float pl[8];
    #pragma unroll
    for (int dd = 0; dd < 8; dd++) pl[dd] = 0.f;

    #pragma unroll
    for (int ii = 0; ii < 4; ii++) {
        float lsum = 0.f, lsq = 0.f;
        #pragma unroll
        for (int dd = 0; dd < 8; dd++) { float x = oacc[ii][dd]; lsum += x; lsq += x * x; }
        lsum += __shfl_xor_sync(0xffffffffu, lsum, 1);
        lsum += __shfl_xor_sync(0xffffffffu, lsum, 2);
        lsum += __shfl_xor_sync(0xffffffffu, lsum, 4);
        lsq  += __shfl_xor_sync(0xffffffffu, lsq, 1);
        lsq  += __shfl_xor_sync(0xffffffffu, lsq, 2);
        lsq  += __shfl_xor_sync(0xffffffffu, lsq, 4);
        float mean = lsum * (1.f / 64.f);
        float var  = lsq * (1.f / 64.f) - mean * mean;
        float rstd = rsqrtf(var + LN_EPS_);
        float mk = (codes[i0 + ii] != 0) ? 1.f : 0.f;
        #pragma unroll
        for (int dd = 0; dd < 8; dd++) {
            float nv = (oacc[ii][dd] - mean) * rstd * garr[dd] + barr[dd];
            pl[dd] += mk * nv;
        }
    }
    #pragma unroll
    for (int dd = 0; dd < 8; dd++) {
        pl[dd] += __shfl_xor_sync(0xffffffffu, pl[dd], 8);
        pl[dd] += __shfl_xor_sync(0xffffffffu, pl[dd], 16);
    }
    if (igrp == 0) {
        float invn = 1.0f / *fnmask;
        #pragma unroll
        for (int dd = 0; dd < 8; dd++) pooledS[h * 64 + d0 + dd] = pl[dd] * invn;
    }
    __syncthreads();

    // ---- MLP per d ----
    if (tid < 64) {
        int d = tid;
        float x[8];
        #pragma unroll
        for (int h2 = 0; h2 < 8; h2++) x[h2] = pooledS[h2 * 64 + d];
        float y1[16];
        #pragma unroll
        for (int k = 0; k < 16; k++) {
            float a = b1[k];
            #pragma unroll
            for (int h2 = 0; h2 < 8; h2++) a += x[h2] * W1[h2 * 16 + k];
            y1[k] = fmaxf(a, 0.f);
        }
        float y2[8];
        #pragma unroll
        for (int m = 0; m < 8; m++) {
            float a = b2[m];
            #pragma unroll
            for (int k = 0; k < 16; k++) a += y1[k] * W2[k * 8 + m];
            y2[m] = a;
        }
        float4* outp = (float4*)&g_wordx[b * 512 + d * 8];
        outp[0] = make_float4(y2[0], y2[1], y2[2], y2[3]);
        outp[1] = make_float4(y2[4], y2[5], y2[6], y2[7]);
    }
}

// ============ kernel 4: PARALLEL counts + exclusive offsets (dtype-robust) ============
__global__ void k_scan(const void* __restrict__ nw_raw, int total) {
    __shared__ long long part[257];
    int t = threadIdx.x;
    const int* p32 = (const int*)nw_raw;

    int v[8];
    long long s = 0;
    bool ok = true;
    #pragma unroll
    for (int k = 0; k < 8; k++) {
        v[k] = p32[t * 8 + k];
        ok = ok && (v[k] >= 0) && (v[k] <= total);
        s += v[k];
    }
    int allok = __syncthreads_and(ok ? 1 : 0);
    part[t] = s;
    __syncthreads();
    if (t == 0) {
        long long a = 0;
        for (int i = 0; i < 256; i++) { long long tmp = part[i]; part[i] = a; a += tmp; }
        part[256] = a;
    }
    __syncthreads();
    bool use32 = allok && (part[256] == (long long)total);

    if (use32) {
        long long a = part[t];
        #pragma unroll
        for (int k = 0; k < 8; k++) {
            g_cnt[t * 8 + k] = v[k];
            g_offs[t * 8 + k] = a;
            a += v[k];
        }
    } else {
        const long long* p64 = (const long long*)nw_raw;
        long long w[8];
        long long s2 = 0;
        #pragma unroll
        for (int k = 0; k < 8; k++) { w[k] = p64[t * 8 + k]; s2 += w[k]; }
        __syncthreads();
        part[t] = s2;
        __syncthreads();
        if (t == 0) {
            long long a = 0;
            for (int i = 0; i < 256; i++) { long long tmp = part[i]; part[i] = a; a += tmp; }
        }
        __syncthreads();
        long long a = part[t];
        #pragma unroll
        for (int k = 0; k < 8; k++) {
            g_cnt[t * 8 + k] = (int)w[k];
            g_offs[t * 8 + k] = a;
            a += w[k];
        }
    }
}

// ============ kernel 5: name segment means (vectorized, 128 threads) ============
__global__ void k_name(const int* __restrict__ word_code,
                       float* __restrict__ out) {
    int n = blockIdx.x;
    int t = threadIdx.x;          // 128 threads, each owns 4 consecutive cols
    int cnt = g_cnt[n];
    long long off = g_offs[n];
    float inv = 1.0f / (float)cnt;
    int c = t * 4;
    float4 acc = make_float4(0.f, 0.f, 0.f, 0.f);
    for (int k = 0; k < cnt; k++) {
        int w = word_code[off + k];
        float4 v = *(const float4*)&g_wordx[w * 512 + c];
        acc.x += v.x; acc.y += v.y; acc.z += v.z; acc.w += v.w;
    }
    acc.x *= inv; acc.y *= inv; acc.z *= inv; acc.w *= inv;
    *(float4*)&out[n * 512 + c] = acc;
}

extern "C" void kernel_launch(void* const* d_in, const int* in_sizes, int n_in,
                              void* d_out, int out_size) {
    const float* char_emb = (const float*)d_in[0];
    const float* Wc       = (const float*)d_in[1];
    const float* bc       = (const float*)d_in[2];
    const float* Wp       = (const float*)d_in[3];
    const float* bp       = (const float*)d_in[4];
    const float* gamma    = (const float*)d_in[5];
    const float* beta     = (const float*)d_in[6];
    const float* W1       = (const float*)d_in[7];
    const float* b1       = (const float*)d_in[8];
    const float* W2       = (const float*)d_in[9];
    const float* b2       = (const float*)d_in[10];
    const int* char_code  = (const int*)d_in[11];
    const int* word_code  = (const int*)d_in[12];
    const void* n_words   = d_in[13];
    (void)n_in; (void)out_size;

    int total_words = in_sizes[12];

    k_pqkv<<<L_, 256>>>(Wp, bp);
    k_posqk<<<H_, 256>>>();
    k_cqkv<<<V_ / 8, 256>>>(char_emb, Wc, bc);   // fused cqkv + T1/T2
    dim3 ggrid(16, 16, 8);
    k_gram<<<ggrid, 256>>>();
    k_scan<<<1, 256>>>(n_words, total_words);
    k_word<<<B_, 256, SMEM_BYTES>>>(char_code, gamma, beta, W1, b1, W2, b2);
    k_name<<<NN_, 128>>>(word_code, (float*)d_out);
}